// round 3
// baseline (speedup 1.0000x reference)
#include <cuda_runtime.h>
#include <math.h>

#define NBT  16      // B*T
#define SLEN 2048
#define HD   64
#define EDIM 256

// Scratch for projected Q/K/V: [bt][s][h], fp32. 8 MB each.
__device__ float g_q[NBT * SLEN * HD];
__device__ float g_k[NBT * SLEN * HD];
__device__ float g_v[NBT * SLEN * HD];

// ---------------------------------------------------------------------------
// Kernel 1: fused QKV projection.  y = x @ W^T + b for Wq, Wk, Wv.
// CTA: 64 tokens, 256 threads. x tile staged once; each W staged in 2 halves.
// ---------------------------------------------------------------------------
#define XPAD 257
#define WPAD 129

__global__ __launch_bounds__(256) void qkv_proj_kernel(
    const float* __restrict__ x,
    const float* __restrict__ Wq, const float* __restrict__ bq,
    const float* __restrict__ Wk, const float* __restrict__ bk,
    const float* __restrict__ Wv, const float* __restrict__ bv)
{
    extern __shared__ float sm[];
    float* xs = sm;                  // [64][XPAD]
    float* ws = sm + 64 * XPAD;      // [64][WPAD]  (half of one W)

    const int tid = threadIdx.x;
    const int t0  = blockIdx.x * 64;

    // Stage x tile [64][256] via float4 (4096 vecs / 256 thr = 16 iters)
    for (int i = tid; i < 4096; i += 256) {
        int r = i >> 6, c4 = i & 63;
        float4 v = *(const float4*)(x + (size_t)(t0 + r) * EDIM + c4 * 4);
        float* d = xs + r * XPAD + c4 * 4;
        d[0] = v.x; d[1] = v.y; d[2] = v.z; d[3] = v.w;
    }

    const int tt = tid >> 4;    // token group 0..15  -> tokens tt*4 .. +3
    const int th = tid & 15;    // h group     0..15  -> h      th*4 .. +3

    const float* Wmat[3] = {Wq, Wk, Wv};
    const float* bias[3] = {bq, bk, bv};
    float* outb[3];
    outb[0] = g_q; outb[1] = g_k; outb[2] = g_v;

    #pragma unroll
    for (int w = 0; w < 3; w++) {
        float acc[4][4];
        #pragma unroll
        for (int i = 0; i < 4; i++)
            #pragma unroll
            for (int j = 0; j < 4; j++) acc[i][j] = 0.f;

        for (int half = 0; half < 2; half++) {
            __syncthreads();
            // Stage W half [64][128] via float4 (2048 vecs / 256 thr = 8 iters)
            for (int i = tid; i < 2048; i += 256) {
                int r = i >> 5, c4 = i & 31;
                float4 v = *(const float4*)(Wmat[w] + r * EDIM + half * 128 + c4 * 4);
                float* d = ws + r * WPAD + c4 * 4;
                d[0] = v.x; d[1] = v.y; d[2] = v.z; d[3] = v.w;
            }
            __syncthreads();
            #pragma unroll 4
            for (int d = 0; d < 128; d++) {
                float xv[4], wv[4];
                #pragma unroll
                for (int i = 0; i < 4; i++)
                    xv[i] = xs[(tt * 4 + i) * XPAD + half * 128 + d];
                #pragma unroll
                for (int j = 0; j < 4; j++)
                    wv[j] = ws[(th * 4 + j) * WPAD + d];
                #pragma unroll
                for (int i = 0; i < 4; i++)
                    #pragma unroll
                    for (int j = 0; j < 4; j++)
                        acc[i][j] += xv[i] * wv[j];
            }
        }

        float* ob = outb[w];
        #pragma unroll
        for (int i = 0; i < 4; i++) {
            const size_t row = (size_t)(t0 + tt * 4 + i) * HD;
            float4 v;
            v.x = acc[i][0] + bias[w][th * 4 + 0];
            v.y = acc[i][1] + bias[w][th * 4 + 1];
            v.z = acc[i][2] + bias[w][th * 4 + 2];
            v.w = acc[i][3] + bias[w][th * 4 + 3];
            *(float4*)(ob + row + th * 4) = v;
        }
    }
}

// ---------------------------------------------------------------------------
// Kernel 2: flash attention + fused output projection.
// CTA: one (bt, 64-query block). 128 threads. Online softmax over 32 KV tiles.
// smem (floats): Qs/Ks/Vs/Ss [64][65], mask [64][64], row stats.
// ---------------------------------------------------------------------------
#define PAD 65
#define QS_OFF 0
#define KS_OFF 4160
#define VS_OFF 8320
#define SS_OFF 12480
#define MS_OFF 16640
#define MR_OFF 20736
#define LR_OFF 20800
#define AR_OFF 20864
#define ATTN_SMEM_FLOATS 20928

__global__ __launch_bounds__(128) void attn_kernel(
    const unsigned int* __restrict__ mask,
    const float* __restrict__ Wo, const float* __restrict__ bo,
    float* __restrict__ out)
{
    extern __shared__ float sm[];
    float* Qs = sm + QS_OFF;
    float* Ks = sm + KS_OFF;
    float* Vs = sm + VS_OFF;
    float* Ss = sm + SS_OFF;
    unsigned int* Mu = (unsigned int*)(sm + MS_OFF);
    float* mrow = sm + MR_OFF;
    float* lrow = sm + LR_OFF;
    float* arow = sm + AR_OFF;

    const int tid = threadIdx.x;
    const int bt  = blockIdx.y;
    const int q0g = blockIdx.x * 64;

    const float* qp = g_q + (size_t)bt * SLEN * HD;
    const float* kp = g_k + (size_t)bt * SLEN * HD;
    const float* vp = g_v + (size_t)bt * SLEN * HD;

    // Stage Q tile [64][64] via float4 (1024 vecs / 128 thr = 8 iters)
    for (int i = tid; i < 1024; i += 128) {
        int r = i >> 4, c4 = i & 15;
        float4 v = *(const float4*)(qp + (size_t)(q0g + r) * HD + c4 * 4);
        float* d = Qs + r * PAD + c4 * 4;
        d[0] = v.x; d[1] = v.y; d[2] = v.z; d[3] = v.w;
    }
    if (tid < 64) { mrow[tid] = -1e30f; lrow[tid] = 0.f; }

    const int tk = tid & 7;    // k/h/g column group -> *8 .. +7
    const int tq = tid >> 3;   // query group 0..15  -> *4 .. +3

    float o[4][8];
    #pragma unroll
    for (int i = 0; i < 4; i++)
        #pragma unroll
        for (int j = 0; j < 8; j++) o[i][j] = 0.f;

    for (int kb = 0; kb < 32; kb++) {
        __syncthreads();
        const int kg0 = kb * 64;
        // Stage K, V tiles via float4
        for (int i = tid; i < 1024; i += 128) {
            int r = i >> 4, c4 = i & 15;
            float4 kv4 = *(const float4*)(kp + (size_t)(kg0 + r) * HD + c4 * 4);
            float4 vv4 = *(const float4*)(vp + (size_t)(kg0 + r) * HD + c4 * 4);
            float* dk = Ks + r * PAD + c4 * 4;
            float* dv = Vs + r * PAD + c4 * 4;
            dk[0] = kv4.x; dk[1] = kv4.y; dk[2] = kv4.z; dk[3] = kv4.w;
            dv[0] = vv4.x; dv[1] = vv4.y; dv[2] = vv4.z; dv[3] = vv4.w;
        }
        // Stage mask tile (nonzero = masked out) via uint4
        const unsigned int* mp = mask + ((size_t)bt * SLEN + q0g) * SLEN + kg0;
        for (int i = tid; i < 1024; i += 128) {
            int r = i >> 4, c4 = i & 15;
            uint4 m4 = *(const uint4*)(mp + (size_t)r * SLEN + c4 * 4);
            *(uint4*)(Mu + r * 64 + c4 * 4) = m4;
        }
        __syncthreads();

        // S = Q K^T * scale, masked
        float s[4][8];
        #pragma unroll
        for (int i = 0; i < 4; i++)
            #pragma unroll
            for (int j = 0; j < 8; j++) s[i][j] = 0.f;
        #pragma unroll 4
        for (int d = 0; d < 64; d++) {
            float qv[4], kv[8];
            #pragma unroll
            for (int i = 0; i < 4; i++) qv[i] = Qs[(tq * 4 + i) * PAD + d];
            #pragma unroll
            for (int j = 0; j < 8; j++) kv[j] = Ks[(tk * 8 + j) * PAD + d];
            #pragma unroll
            for (int i = 0; i < 4; i++)
                #pragma unroll
                for (int j = 0; j < 8; j++) s[i][j] += qv[i] * kv[j];
        }
        #pragma unroll
        for (int i = 0; i < 4; i++) {
            const int q = tq * 4 + i;
            #pragma unroll
            for (int j = 0; j < 8; j++) {
                const int k = tk * 8 + j;
                // scale = 1/sqrt(E) = 1/16 (reference scales by n_embd, not head)
                Ss[q * PAD + k] = Mu[q * 64 + k] ? -10000000.0f
                                                 : s[i][j] * 0.0625f;
            }
        }
        __syncthreads();

        // Online softmax: 2 threads per row
        {
            const int r = tid >> 1;
            float* row = Ss + r * PAD + (tid & 1) * 32;
            float mloc = -1e30f;
            #pragma unroll 8
            for (int c = 0; c < 32; c++) mloc = fmaxf(mloc, row[c]);
            mloc = fmaxf(mloc, __shfl_xor_sync(0xffffffffu, mloc, 1));
            const float mold = mrow[r];
            const float mnew = fmaxf(mold, mloc);
            float ssum = 0.f;
            #pragma unroll 8
            for (int c = 0; c < 32; c++) {
                float p = __expf(row[c] - mnew);
                row[c] = p;
                ssum += p;
            }
            ssum += __shfl_xor_sync(0xffffffffu, ssum, 1);
            if ((tid & 1) == 0) {
                const float al = __expf(mold - mnew);
                arow[r] = al;
                lrow[r] = lrow[r] * al + ssum;
                mrow[r] = mnew;
            }
        }
        __syncthreads();

        // O = O*alpha + P @ V
        #pragma unroll
        for (int i = 0; i < 4; i++) {
            const float al = arow[tq * 4 + i];
            #pragma unroll
            for (int j = 0; j < 8; j++) o[i][j] *= al;
        }
        #pragma unroll 4
        for (int k = 0; k < 64; k++) {
            float pv[4], vv[8];
            #pragma unroll
            for (int i = 0; i < 4; i++) pv[i] = Ss[(tq * 4 + i) * PAD + k];
            #pragma unroll
            for (int j = 0; j < 8; j++) vv[j] = Vs[k * PAD + tk * 8 + j];
            #pragma unroll
            for (int i = 0; i < 4; i++)
                #pragma unroll
                for (int j = 0; j < 8; j++) o[i][j] += pv[i] * vv[j];
        }
    }
    __syncthreads();

    // Stage normalized O into Ss; stage Wo into the freed K buffer (pad 65)
    #pragma unroll
    for (int i = 0; i < 4; i++) {
        const float inv = 1.0f / lrow[tq * 4 + i];
        #pragma unroll
        for (int j = 0; j < 8; j++)
            Ss[(tq * 4 + i) * PAD + tk * 8 + j] = o[i][j] * inv;
    }
    for (int i = tid; i < 1024; i += 128) {
        int r = i >> 4, c4 = i & 15;
        float4 v = *(const float4*)(Wo + r * HD + c4 * 4);
        float* d = Ks + r * PAD + c4 * 4;
        d[0] = v.x; d[1] = v.y; d[2] = v.z; d[3] = v.w;
    }
    if (tid < 64) arow[tid] = bo[tid];
    __syncthreads();

    // out[q][g] = sum_h O[q][h] * Wo[g][h] + bo[g]
    float r2[4][8];
    #pragma unroll
    for (int i = 0; i < 4; i++)
        #pragma unroll
        for (int j = 0; j < 8; j++) r2[i][j] = 0.f;
    #pragma unroll 4
    for (int h = 0; h < 64; h++) {
        float ov[4], wv[8];
        #pragma unroll
        for (int i = 0; i < 4; i++) ov[i] = Ss[(tq * 4 + i) * PAD + h];
        #pragma unroll
        for (int j = 0; j < 8; j++) wv[j] = Ks[(tk * 8 + j) * PAD + h];
        #pragma unroll
        for (int i = 0; i < 4; i++)
            #pragma unroll
            for (int j = 0; j < 8; j++) r2[i][j] += ov[i] * wv[j];
    }
    #pragma unroll
    for (int i = 0; i < 4; i++) {
        const size_t row = ((size_t)bt * SLEN + q0g + tq * 4 + i) * HD;
        float4 a, b;
        a.x = r2[i][0] + arow[tk * 8 + 0];
        a.y = r2[i][1] + arow[tk * 8 + 1];
        a.z = r2[i][2] + arow[tk * 8 + 2];
        a.w = r2[i][3] + arow[tk * 8 + 3];
        b.x = r2[i][4] + arow[tk * 8 + 4];
        b.y = r2[i][5] + arow[tk * 8 + 5];
        b.z = r2[i][6] + arow[tk * 8 + 6];
        b.w = r2[i][7] + arow[tk * 8 + 7];
        *(float4*)(out + row + tk * 8 + 0) = a;
        *(float4*)(out + row + tk * 8 + 4) = b;
    }
}

// ---------------------------------------------------------------------------
// Launch
// ---------------------------------------------------------------------------
extern "C" void kernel_launch(void* const* d_in, const int* in_sizes, int n_in,
                              void* d_out, int out_size)
{
    const float*        x    = (const float*)d_in[0];
    const unsigned int* mask = (const unsigned int*)d_in[1];
    const float*        Wq   = (const float*)d_in[2];
    const float*        bq   = (const float*)d_in[3];
    const float*        Wk   = (const float*)d_in[4];
    const float*        bk   = (const float*)d_in[5];
    const float*        Wv   = (const float*)d_in[6];
    const float*        bv   = (const float*)d_in[7];
    const float*        Wo   = (const float*)d_in[8];
    const float*        bo   = (const float*)d_in[9];
    float*              out  = (float*)d_out;

    const int proj_smem = (64 * XPAD + 64 * WPAD) * (int)sizeof(float);   // ~98.8 KB
    const int attn_smem = ATTN_SMEM_FLOATS * (int)sizeof(float);          // ~83.7 KB

    cudaFuncSetAttribute(qkv_proj_kernel,
                         cudaFuncAttributeMaxDynamicSharedMemorySize, proj_smem);
    cudaFuncSetAttribute(attn_kernel,
                         cudaFuncAttributeMaxDynamicSharedMemorySize, attn_smem);

    // 32768 tokens / 64 per CTA
    qkv_proj_kernel<<<512, 256, proj_smem>>>(x, Wq, bq, Wk, bk, Wv, bv);
    // 32 query-blocks x 16 (b,t) pairs
    attn_kernel<<<dim3(32, 16), 128, attn_smem>>>(mask, Wo, bo, out);
}

// round 5
// speedup vs baseline: 1.2604x; 1.2604x over previous
#include <cuda_runtime.h>
#include <math.h>

#define NBT  16
#define SLEN 2048
#define HD   64
#define EDIM 256

// Q,K stored TRANSPOSED per bt: [bt][d][s]  (enables cp.async + vector LDS in attn)
__device__ float g_qT[NBT * HD * SLEN];
__device__ float g_kT[NBT * HD * SLEN];
// V row-major: [bt][s][h]
__device__ float g_v [NBT * SLEN * HD];

// ---------------- f32x2 helpers ----------------
typedef unsigned long long ull;

__device__ __forceinline__ void ffma2(ull& d, ull a, ull b) {
    asm("fma.rn.f32x2 %0, %1, %2, %0;" : "+l"(d) : "l"(a), "l"(b));
}
__device__ __forceinline__ ull mul2(ull a, ull b) {
    ull r; asm("mul.rn.f32x2 %0, %1, %2;" : "=l"(r) : "l"(a), "l"(b)); return r;
}
__device__ __forceinline__ ull dup2(float x) {
    ull r; asm("mov.b64 %0, {%1, %1};" : "=l"(r) : "f"(x)); return r;
}
__device__ __forceinline__ ull pk2(float lo, float hi) {
    ull r; asm("mov.b64 %0, {%1, %2};" : "=l"(r) : "f"(lo), "f"(hi)); return r;
}
__device__ __forceinline__ void upk2(float& lo, float& hi, ull v) {
    asm("mov.b64 {%0, %1}, %2;" : "=f"(lo), "=f"(hi) : "l"(v));
}
__device__ __forceinline__ void cp16(unsigned int dst_smem, const void* src) {
    asm volatile("cp.async.cg.shared.global [%0], [%1], 16;" :: "r"(dst_smem), "l"(src));
}
__device__ __forceinline__ void cp_commit() { asm volatile("cp.async.commit_group;"); }
__device__ __forceinline__ void cp_wait0()  { asm volatile("cp.async.wait_group 0;"); }

// ---------------------------------------------------------------------------
// Kernel 1: QKV projection with f32x2.  CTA = 64 tokens, 256 threads.
// Q,K written transposed [bt][d][s]; V row-major.
// ---------------------------------------------------------------------------
#define XPAD 257

__global__ __launch_bounds__(256) void qkv_proj_kernel(
    const float* __restrict__ x,
    const float* __restrict__ Wq, const float* __restrict__ bq,
    const float* __restrict__ Wk, const float* __restrict__ bk,
    const float* __restrict__ Wv, const float* __restrict__ bv)
{
    extern __shared__ float sm[];
    float* xs  = sm;                 // [64][257]
    float* wsT = sm + 64 * XPAD;     // [128 d][64 h]  (one half of W, transposed)

    const int tid = threadIdx.x;
    const int t0  = blockIdx.x * 64;

    // Stage x [64][256] (float4 loads, scalar stores: 257-stride unaligned)
    for (int i = tid; i < 4096; i += 256) {
        int r = i >> 6, c4 = i & 63;
        float4 v = *(const float4*)(x + (size_t)(t0 + r) * EDIM + c4 * 4);
        float* d = xs + r * XPAD + c4 * 4;
        d[0] = v.x; d[1] = v.y; d[2] = v.z; d[3] = v.w;
    }

    const int tt = tid >> 4;   // token group 0..15 -> tokens tt*4..+3
    const int th = tid & 15;   // h group 0..15     -> h th*4..+3

    const float* Wmat[3] = {Wq, Wk, Wv};
    const float* bias[3] = {bq, bk, bv};

    for (int w = 0; w < 3; w++) {
        ull acc[4][2];
        #pragma unroll
        for (int i = 0; i < 4; i++) { acc[i][0] = 0ull; acc[i][1] = 0ull; }

        for (int half = 0; half < 2; half++) {
            __syncthreads();
            // Stage W-half transposed: wsT[d][h] <- W[h][half*128+d]
            for (int i = tid; i < 2048; i += 256) {
                int h = i & 63, d4 = i >> 6;          // d4 0..31
                float4 v = *(const float4*)(Wmat[w] + h * EDIM + half * 128 + d4 * 4);
                wsT[(d4 * 4 + 0) * 64 + h] = v.x;
                wsT[(d4 * 4 + 1) * 64 + h] = v.y;
                wsT[(d4 * 4 + 2) * 64 + h] = v.z;
                wsT[(d4 * 4 + 3) * 64 + h] = v.w;
            }
            __syncthreads();
            #pragma unroll 4
            for (int d = 0; d < 128; d++) {
                ulonglong2 wv = *(const ulonglong2*)(wsT + d * 64 + th * 4);
                #pragma unroll
                for (int i = 0; i < 4; i++) {
                    ull xd = dup2(xs[(tt * 4 + i) * XPAD + half * 128 + d]);
                    ffma2(acc[i][0], xd, wv.x);
                    ffma2(acc[i][1], xd, wv.y);
                }
            }
        }

        // Write out
        #pragma unroll
        for (int i = 0; i < 4; i++) {
            const int token = t0 + tt * 4 + i;
            float v0, v1, v2, v3;
            upk2(v0, v1, acc[i][0]);
            upk2(v2, v3, acc[i][1]);
            v0 += bias[w][th * 4 + 0];
            v1 += bias[w][th * 4 + 1];
            v2 += bias[w][th * 4 + 2];
            v3 += bias[w][th * 4 + 3];
            if (w == 2) {
                float4 o; o.x = v0; o.y = v1; o.z = v2; o.w = v3;
                *(float4*)(g_v + (size_t)token * HD + th * 4) = o;
            } else {
                float* gT = (w == 0 ? g_qT : g_kT);
                const int bt = token >> 11, sl = token & 2047;
                float* base = gT + (size_t)bt * HD * SLEN + sl;
                base[(th * 4 + 0) * SLEN] = v0;
                base[(th * 4 + 1) * SLEN] = v1;
                base[(th * 4 + 2) * SLEN] = v2;
                base[(th * 4 + 3) * SLEN] = v3;
            }
        }
    }
}

// ---------------------------------------------------------------------------
// Kernel 2: flash attention + fused Wo.  CTA = 128 queries, 256 threads.
// Qs[d][q] 64x128; Ks[d][k] 64x64 x2 buf; Vs[k][h] 64x64 x2 buf; Ps[q][k] 128x64.
// Warp-local softmax (shfl over 8-lane row groups); mask direct from gmem.
// ---------------------------------------------------------------------------
#define QS_OFF 0
#define KS_OFF 8192
#define VS_OFF 16384
#define PS_OFF 24576
#define BO_OFF 32768
#define ATTN_FLOATS 32832

__global__ __launch_bounds__(256) void attn_kernel(
    const unsigned int* __restrict__ mask,
    const float* __restrict__ Wo, const float* __restrict__ bo,
    float* __restrict__ out)
{
    extern __shared__ float sm[];
    float* Qs = sm + QS_OFF;
    float* Ks = sm + KS_OFF;   // + buf*4096
    float* Vs = sm + VS_OFF;   // + buf*4096
    float* Ps = sm + PS_OFF;
    float* bos = sm + BO_OFF;
    const unsigned int smem_u32 = (unsigned int)__cvta_generic_to_shared(sm);

    const int tid = threadIdx.x;
    const int bt  = blockIdx.y;
    const int q0g = blockIdx.x * 128;

    const int tq = tid >> 3;           // 0..31 -> rows 4tq..+3 (local)
    const int tk = tid & 7;            // 0..7  -> cols 8tk..+7
    const int sw = (tq & 3) << 1;      // Ps XOR swizzle for this thread's rows

    const float* qT = g_qT + (size_t)bt * HD * SLEN;
    const float* kT = g_kT + (size_t)bt * HD * SLEN;
    const float* vP = g_v  + (size_t)bt * SLEN * HD;

    // ---- prologue: cp.async Q tile + K/V tile 0, one group ----
    for (int c = tid; c < 2048; c += 256) {          // Qs[d][q] 64x128
        int d = c >> 5, q4 = c & 31;
        cp16(smem_u32 + (QS_OFF + d * 128 + q4 * 4) * 4, qT + d * SLEN + q0g + q4 * 4);
    }
    for (int c = tid; c < 1024; c += 256) {          // Ks buf0 [d][k]
        int d = c >> 4, k4 = c & 15;
        cp16(smem_u32 + (KS_OFF + d * 64 + k4 * 4) * 4, kT + d * SLEN + k4 * 4);
    }
    for (int c = tid; c < 1024; c += 256) {          // Vs buf0 [k][h]
        int k = c >> 4, h4 = c & 15;
        cp16(smem_u32 + (VS_OFF + k * 64 + h4 * 4) * 4, vP + (size_t)k * HD + h4 * 4);
    }
    cp_commit();

    float m_run[4], l_run[4];
    #pragma unroll
    for (int i = 0; i < 4; i++) { m_run[i] = -1e30f; l_run[i] = 0.f; }
    ull o2[4][4];
    #pragma unroll
    for (int i = 0; i < 4; i++)
        #pragma unroll
        for (int jj = 0; jj < 4; jj++) o2[i][jj] = 0ull;

    const uint4* mrow_base = (const uint4*)(mask + ((size_t)bt * SLEN + q0g) * SLEN);

    for (int kb = 0; kb < 32; kb++) {
        const int buf = kb & 1;
        cp_wait0();
        __syncthreads();

        // issue next tile into other buffer (overlaps with compute below)
        if (kb + 1 < 32) {
            const int nb = buf ^ 1, kg1 = (kb + 1) * 64;
            for (int c = tid; c < 1024; c += 256) {
                int d = c >> 4, k4 = c & 15;
                cp16(smem_u32 + (KS_OFF + nb * 4096 + d * 64 + k4 * 4) * 4,
                     kT + d * SLEN + kg1 + k4 * 4);
            }
            for (int c = tid; c < 1024; c += 256) {
                int k = c >> 4, h4 = c & 15;
                cp16(smem_u32 + (VS_OFF + nb * 4096 + k * 64 + h4 * 4) * 4,
                     vP + (size_t)(kg1 + k) * HD + h4 * 4);
            }
            cp_commit();
        }

        // mask prefetch (consumed ~2000 cyc later)
        uint4 mreg[4][2];
        #pragma unroll
        for (int i = 0; i < 4; i++) {
            const uint4* mp = mrow_base + ((size_t)(tq * 4 + i) * SLEN + kb * 64 + tk * 8) / 4;
            mreg[i][0] = mp[0];
            mreg[i][1] = mp[1];
        }

        // ---- S = Q K^T (f32x2, pairs along k) ----
        const float* Kb = Ks + buf * 4096;
        ull s2[4][4];
        #pragma unroll
        for (int i = 0; i < 4; i++)
            #pragma unroll
            for (int jj = 0; jj < 4; jj++) s2[i][jj] = 0ull;

        #pragma unroll 4
        for (int d = 0; d < 64; d++) {
            ulonglong2 ka = *(const ulonglong2*)(Kb + d * 64 + tk * 8);
            ulonglong2 kb2 = *(const ulonglong2*)(Kb + d * 64 + tk * 8 + 4);
            float4 q4 = *(const float4*)(Qs + d * 128 + tq * 4);
            ull qd0 = dup2(q4.x), qd1 = dup2(q4.y), qd2 = dup2(q4.z), qd3 = dup2(q4.w);
            ffma2(s2[0][0], qd0, ka.x); ffma2(s2[0][1], qd0, ka.y);
            ffma2(s2[0][2], qd0, kb2.x); ffma2(s2[0][3], qd0, kb2.y);
            ffma2(s2[1][0], qd1, ka.x); ffma2(s2[1][1], qd1, ka.y);
            ffma2(s2[1][2], qd1, kb2.x); ffma2(s2[1][3], qd1, kb2.y);
            ffma2(s2[2][0], qd2, ka.x); ffma2(s2[2][1], qd2, ka.y);
            ffma2(s2[2][2], qd2, kb2.x); ffma2(s2[2][3], qd2, kb2.y);
            ffma2(s2[3][0], qd3, ka.x); ffma2(s2[3][1], qd3, ka.y);
            ffma2(s2[3][2], qd3, kb2.x); ffma2(s2[3][3], qd3, kb2.y);
        }

        // ---- per-row warp-local softmax (rows owned by 8-lane groups) ----
        #pragma unroll
        for (int i = 0; i < 4; i++) {
            float sv[8];
            upk2(sv[0], sv[1], s2[i][0]); upk2(sv[2], sv[3], s2[i][1]);
            upk2(sv[4], sv[5], s2[i][2]); upk2(sv[6], sv[7], s2[i][3]);
            const unsigned int mk[8] = {mreg[i][0].x, mreg[i][0].y, mreg[i][0].z, mreg[i][0].w,
                                        mreg[i][1].x, mreg[i][1].y, mreg[i][1].z, mreg[i][1].w};
            #pragma unroll
            for (int j = 0; j < 8; j++)
                sv[j] = mk[j] ? -10000000.0f : sv[j] * 0.0625f;
            float mloc = sv[0];
            #pragma unroll
            for (int j = 1; j < 8; j++) mloc = fmaxf(mloc, sv[j]);
            mloc = fmaxf(mloc, __shfl_xor_sync(0xffffffffu, mloc, 1));
            mloc = fmaxf(mloc, __shfl_xor_sync(0xffffffffu, mloc, 2));
            mloc = fmaxf(mloc, __shfl_xor_sync(0xffffffffu, mloc, 4));
            const float mnew = fmaxf(m_run[i], mloc);
            const float alpha = __expf(m_run[i] - mnew);
            float rs = 0.f;
            #pragma unroll
            for (int j = 0; j < 8; j++) { sv[j] = __expf(sv[j] - mnew); rs += sv[j]; }
            rs += __shfl_xor_sync(0xffffffffu, rs, 1);
            rs += __shfl_xor_sync(0xffffffffu, rs, 2);
            rs += __shfl_xor_sync(0xffffffffu, rs, 4);
            l_run[i] = l_run[i] * alpha + rs;
            m_run[i] = mnew;
            const ull ad = dup2(alpha);
            o2[i][0] = mul2(o2[i][0], ad); o2[i][1] = mul2(o2[i][1], ad);
            o2[i][2] = mul2(o2[i][2], ad); o2[i][3] = mul2(o2[i][3], ad);
            // write P (swizzled)
            float* pr = Ps + (tq * 4 + i) * 64;
            #pragma unroll
            for (int jj = 0; jj < 4; jj++)
                *(ull*)(pr + ((tk * 8 + jj * 2) ^ sw)) = pk2(sv[jj * 2], sv[jj * 2 + 1]);
        }
        __syncwarp();

        // ---- O += P V (f32x2, pairs along h) ----
        const float* Vb = Vs + buf * 4096;
        #pragma unroll 4
        for (int k = 0; k < 64; k++) {
            ulonglong2 va = *(const ulonglong2*)(Vb + k * 64 + tk * 8);
            ulonglong2 vb = *(const ulonglong2*)(Vb + k * 64 + tk * 8 + 4);
            const int kx = k ^ sw;
            ull p0 = dup2(Ps[(tq * 4 + 0) * 64 + kx]);
            ull p1 = dup2(Ps[(tq * 4 + 1) * 64 + kx]);
            ull p2 = dup2(Ps[(tq * 4 + 2) * 64 + kx]);
            ull p3 = dup2(Ps[(tq * 4 + 3) * 64 + kx]);
            ffma2(o2[0][0], p0, va.x); ffma2(o2[0][1], p0, va.y);
            ffma2(o2[0][2], p0, vb.x); ffma2(o2[0][3], p0, vb.y);
            ffma2(o2[1][0], p1, va.x); ffma2(o2[1][1], p1, va.y);
            ffma2(o2[1][2], p1, vb.x); ffma2(o2[1][3], p1, vb.y);
            ffma2(o2[2][0], p2, va.x); ffma2(o2[2][1], p2, va.y);
            ffma2(o2[2][2], p2, vb.x); ffma2(o2[2][3], p2, vb.y);
            ffma2(o2[3][0], p3, va.x); ffma2(o2[3][1], p3, va.y);
            ffma2(o2[3][2], p3, vb.x); ffma2(o2[3][3], p3, vb.y);
        }
    }

    // ---- normalize O into Ps (same swizzle) ----
    #pragma unroll
    for (int i = 0; i < 4; i++) {
        const float inv = 1.0f / l_run[i];
        float* pr = Ps + (tq * 4 + i) * 64;
        #pragma unroll
        for (int jj = 0; jj < 4; jj++) {
            float lo, hi; upk2(lo, hi, o2[i][jj]);
            *(ull*)(pr + ((tk * 8 + jj * 2) ^ sw)) = pk2(lo * inv, hi * inv);
        }
    }
    __syncthreads();

    // stage WoT[h][g] into Ks buf0 (free: no cp.async pending there)
    float* WoT = Ks;
    for (int i = tid; i < 1024; i += 256) {
        int g = i & 63, h4 = i >> 6;   // h4 0..15
        float4 v = *(const float4*)(Wo + g * HD + h4 * 4);
        WoT[(h4 * 4 + 0) * 64 + g] = v.x;
        WoT[(h4 * 4 + 1) * 64 + g] = v.y;
        WoT[(h4 * 4 + 2) * 64 + g] = v.z;
        WoT[(h4 * 4 + 3) * 64 + g] = v.w;
    }
    if (tid < 64) bos[tid] = bo[tid];
    __syncthreads();

    // ---- out = O_norm @ Wo^T + bo  (f32x2, pairs along g) ----
    ull r2[4][4];
    #pragma unroll
    for (int i = 0; i < 4; i++)
        #pragma unroll
        for (int jj = 0; jj < 4; jj++) r2[i][jj] = 0ull;
    #pragma unroll 4
    for (int h = 0; h < 64; h++) {
        ulonglong2 wa = *(const ulonglong2*)(WoT + h * 64 + tk * 8);
        ulonglong2 wb = *(const ulonglong2*)(WoT + h * 64 + tk * 8 + 4);
        const int hx = h ^ sw;
        ull v0 = dup2(Ps[(tq * 4 + 0) * 64 + hx]);
        ull v1 = dup2(Ps[(tq * 4 + 1) * 64 + hx]);
        ull v2 = dup2(Ps[(tq * 4 + 2) * 64 + hx]);
        ull v3 = dup2(Ps[(tq * 4 + 3) * 64 + hx]);
        ffma2(r2[0][0], v0, wa.x); ffma2(r2[0][1], v0, wa.y);
        ffma2(r2[0][2], v0, wb.x); ffma2(r2[0][3], v0, wb.y);
        ffma2(r2[1][0], v1, wa.x); ffma2(r2[1][1], v1, wa.y);
        ffma2(r2[1][2], v1, wb.x); ffma2(r2[1][3], v1, wb.y);
        ffma2(r2[2][0], v2, wa.x); ffma2(r2[2][1], v2, wa.y);
        ffma2(r2[2][2], v2, wb.x); ffma2(r2[2][3], v2, wb.y);
        ffma2(r2[3][0], v3, wa.x); ffma2(r2[3][1], v3, wa.y);
        ffma2(r2[3][2], v3, wb.x); ffma2(r2[3][3], v3, wb.y);
    }
    #pragma unroll
    for (int i = 0; i < 4; i++) {
        float g0, g1, g2, g3, g4, g5, g6, g7;
        upk2(g0, g1, r2[i][0]); upk2(g2, g3, r2[i][1]);
        upk2(g4, g5, r2[i][2]); upk2(g6, g7, r2[i][3]);
        float4 a, b;
        a.x = g0 + bos[tk * 8 + 0]; a.y = g1 + bos[tk * 8 + 1];
        a.z = g2 + bos[tk * 8 + 2]; a.w = g3 + bos[tk * 8 + 3];
        b.x = g4 + bos[tk * 8 + 4]; b.y = g5 + bos[tk * 8 + 5];
        b.z = g6 + bos[tk * 8 + 6]; b.w = g7 + bos[tk * 8 + 7];
        float* orow = out + ((size_t)bt * SLEN + q0g + tq * 4 + i) * HD + tk * 8;
        *(float4*)(orow + 0) = a;
        *(float4*)(orow + 4) = b;
    }
}

// ---------------------------------------------------------------------------
extern "C" void kernel_launch(void* const* d_in, const int* in_sizes, int n_in,
                              void* d_out, int out_size)
{
    const float*        x    = (const float*)d_in[0];
    const unsigned int* mask = (const unsigned int*)d_in[1];
    const float*        Wq   = (const float*)d_in[2];
    const float*        bq   = (const float*)d_in[3];
    const float*        Wk   = (const float*)d_in[4];
    const float*        bk   = (const float*)d_in[5];
    const float*        Wv   = (const float*)d_in[6];
    const float*        bv   = (const float*)d_in[7];
    const float*        Wo   = (const float*)d_in[8];
    const float*        bo   = (const float*)d_in[9];
    float*              out  = (float*)d_out;

    const int proj_smem = (64 * XPAD + 128 * 64) * (int)sizeof(float);  // ~97.8 KB
    const int attn_smem = ATTN_FLOATS * (int)sizeof(float);             // ~128.3 KB

    cudaFuncSetAttribute(qkv_proj_kernel,
                         cudaFuncAttributeMaxDynamicSharedMemorySize, proj_smem);
    cudaFuncSetAttribute(attn_kernel,
                         cudaFuncAttributeMaxDynamicSharedMemorySize, attn_smem);

    qkv_proj_kernel<<<512, 256, proj_smem>>>(x, Wq, bq, Wk, bk, Wv, bv);
    attn_kernel<<<dim3(16, 16), 256, attn_smem>>>(mask, Wo, bo, out);
}

// round 8
// speedup vs baseline: 3.0784x; 2.4424x over previous
#include <cuda_runtime.h>
#include <math.h>

#define NBT  16
#define SLEN 2048
#define HD   64
#define EDIM 256

// Projections, all row-major [bt*S + s][h], tf32-rounded.
__device__ float g_q[NBT * SLEN * HD];
__device__ float g_k[NBT * SLEN * HD];
__device__ float g_v[NBT * SLEN * HD];

typedef unsigned long long ull;
typedef unsigned int u32;

// ---------------- helpers ----------------
__device__ __forceinline__ void ffma2(ull& d, ull a, ull b) {
    asm("fma.rn.f32x2 %0, %1, %2, %0;" : "+l"(d) : "l"(a), "l"(b));
}
__device__ __forceinline__ ull dup2(float x) {
    ull r; asm("mov.b64 %0, {%1, %1};" : "=l"(r) : "f"(x)); return r;
}
__device__ __forceinline__ void upk2(float& lo, float& hi, ull v) {
    asm("mov.b64 {%0, %1}, %2;" : "=f"(lo), "=f"(hi) : "l"(v));
}
__device__ __forceinline__ float to_tf32(float x) {
    u32 r; asm("cvt.rna.tf32.f32 %0, %1;" : "=r"(r) : "f"(x));
    return __uint_as_float(r);
}
__device__ __forceinline__ void cp16(u32 dst, const void* src) {
    asm volatile("cp.async.cg.shared.global [%0], [%1], 16;" :: "r"(dst), "l"(src));
}
__device__ __forceinline__ void cp_commit() { asm volatile("cp.async.commit_group;"); }
__device__ __forceinline__ void cp_wait1()  { asm volatile("cp.async.wait_group 1;"); }
__device__ __forceinline__ void cp_wait0()  { asm volatile("cp.async.wait_group 0;"); }

// m16n8k8 tf32 warp MMA:  C(16x8) += A(16x8) * B(8x8)
__device__ __forceinline__ void mma8(float c[4], const u32 a[4], u32 b0, u32 b1) {
    asm volatile(
        "mma.sync.aligned.m16n8k8.row.col.f32.tf32.tf32.f32 "
        "{%0,%1,%2,%3}, {%4,%5,%6,%7}, {%8,%9}, {%0,%1,%2,%3};"
        : "+f"(c[0]), "+f"(c[1]), "+f"(c[2]), "+f"(c[3])
        : "r"(a[0]), "r"(a[1]), "r"(a[2]), "r"(a[3]), "r"(b0), "r"(b1));
}

// ---------------------------------------------------------------------------
// Kernel 1: QKV projection (f32x2), tf32-rounded row-major outputs.
// ---------------------------------------------------------------------------
#define XPAD 257

__global__ __launch_bounds__(256) void qkv_proj_kernel(
    const float* __restrict__ x,
    const float* __restrict__ Wq, const float* __restrict__ bq,
    const float* __restrict__ Wk, const float* __restrict__ bk,
    const float* __restrict__ Wv, const float* __restrict__ bv)
{
    extern __shared__ float sm[];
    float* xs  = sm;                 // [64][257]
    float* wsT = sm + 64 * XPAD;     // [128 d][64 h]

    const int tid = threadIdx.x;
    const int t0  = blockIdx.x * 64;

    for (int i = tid; i < 4096; i += 256) {
        int r = i >> 6, c4 = i & 63;
        float4 v = *(const float4*)(x + (size_t)(t0 + r) * EDIM + c4 * 4);
        float* d = xs + r * XPAD + c4 * 4;
        d[0] = v.x; d[1] = v.y; d[2] = v.z; d[3] = v.w;
    }

    const int tt = tid >> 4;
    const int th = tid & 15;

    const float* Wmat[3] = {Wq, Wk, Wv};
    const float* bias[3] = {bq, bk, bv};
    float* outb[3];
    outb[0] = g_q; outb[1] = g_k; outb[2] = g_v;

    for (int w = 0; w < 3; w++) {
        ull acc[4][2];
        #pragma unroll
        for (int i = 0; i < 4; i++) { acc[i][0] = 0ull; acc[i][1] = 0ull; }

        for (int half = 0; half < 2; half++) {
            __syncthreads();
            for (int i = tid; i < 2048; i += 256) {
                int h = i & 63, d4 = i >> 6;
                float4 v = *(const float4*)(Wmat[w] + h * EDIM + half * 128 + d4 * 4);
                wsT[(d4 * 4 + 0) * 64 + h] = v.x;
                wsT[(d4 * 4 + 1) * 64 + h] = v.y;
                wsT[(d4 * 4 + 2) * 64 + h] = v.z;
                wsT[(d4 * 4 + 3) * 64 + h] = v.w;
            }
            __syncthreads();
            #pragma unroll 4
            for (int d = 0; d < 128; d++) {
                ulonglong2 wv = *(const ulonglong2*)(wsT + d * 64 + th * 4);
                #pragma unroll
                for (int i = 0; i < 4; i++) {
                    ull xd = dup2(xs[(tt * 4 + i) * XPAD + half * 128 + d]);
                    ffma2(acc[i][0], xd, wv.x);
                    ffma2(acc[i][1], xd, wv.y);
                }
            }
        }

        #pragma unroll
        for (int i = 0; i < 4; i++) {
            const int token = t0 + tt * 4 + i;
            float v0, v1, v2, v3;
            upk2(v0, v1, acc[i][0]);
            upk2(v2, v3, acc[i][1]);
            float4 o;
            o.x = to_tf32(v0 + bias[w][th * 4 + 0]);
            o.y = to_tf32(v1 + bias[w][th * 4 + 1]);
            o.z = to_tf32(v2 + bias[w][th * 4 + 2]);
            o.w = to_tf32(v3 + bias[w][th * 4 + 3]);
            *(float4*)(outb[w] + (size_t)token * HD + th * 4) = o;
        }
    }
}

// ---------------------------------------------------------------------------
// Kernel 2: warp-MMA tf32 flash attention + fused Wo.
// CTA = 128 queries, 8 warps. Warp w owns query rows w*16..w*16+15.
// ---------------------------------------------------------------------------
#define KS_OFF 0
#define KSTRIDE 68
#define KBUF 4352            // 64*68
#define VS_OFF 8704
#define VSTRIDE 72
#define VBUF 4608            // 64*72
#define PS_OFF 17920
#define PSTRIDE 72
#define BO_OFF 27136
#define ATTN_FLOATS 27200    // 108.8 KB

#define SCALE 0.0625f

__global__ __launch_bounds__(256) void attn_mma_kernel(
    const u32* __restrict__ mask,
    const float* __restrict__ Wo, const float* __restrict__ bo,
    float* __restrict__ out)
{
    extern __shared__ float sm[];
    float* Ks = sm + KS_OFF;
    float* Vs = sm + VS_OFF;
    float* Ps = sm + PS_OFF;
    float* bos = sm + BO_OFF;
    const u32 sb = (u32)__cvta_generic_to_shared(sm);

    const int tid  = threadIdx.x;
    const int wid  = tid >> 5;
    const int lane = tid & 31;
    const int g    = lane >> 2;   // 0..7
    const int q    = lane & 3;    // 0..3
    const int bt   = blockIdx.y;
    const int q0   = blockIdx.x * 128;

    const int r0 = wid * 16 + g;        // local query rows
    const int r1 = r0 + 8;
    const size_t qg0 = (size_t)bt * SLEN + q0 + r0;
    const size_t qg1 = qg0 + 8;

    const float* kbase = g_k + ((size_t)bt * SLEN) * HD;
    const float* vbase = g_v + ((size_t)bt * SLEN) * HD;

    // ---- Q A-fragments, resident for whole kernel ----
    u32 qa[8][4];
    {
        const float* qrow0 = g_q + qg0 * HD;
        const float* qrow1 = g_q + qg1 * HD;
        #pragma unroll
        for (int kc = 0; kc < 8; kc++) {
            qa[kc][0] = __float_as_uint(__ldg(qrow0 + kc * 8 + q));
            qa[kc][1] = __float_as_uint(__ldg(qrow1 + kc * 8 + q));
            qa[kc][2] = __float_as_uint(__ldg(qrow0 + kc * 8 + q + 4));
            qa[kc][3] = __float_as_uint(__ldg(qrow1 + kc * 8 + q + 4));
        }
    }

    // ---- stage tile 0 (K pad 68, V pad 72) ----
    for (int i = tid; i < 1024; i += 256) {
        int r = i >> 4, c = i & 15;
        cp16(sb + (KS_OFF + r * KSTRIDE + c * 4) * 4, kbase + (size_t)r * HD + c * 4);
        cp16(sb + (VS_OFF + r * VSTRIDE + c * 4) * 4, vbase + (size_t)r * HD + c * 4);
    }
    cp_commit();

    if (tid < 64) bos[tid] = bo[tid];

    float oc[8][4];
    #pragma unroll
    for (int nb = 0; nb < 8; nb++)
        #pragma unroll
        for (int j = 0; j < 4; j++) oc[nb][j] = 0.f;
    float l0 = 0.f, l1 = 0.f;

    const u32* mrow0 = mask + qg0 * SLEN;
    const u32* mrow1 = mask + qg1 * SLEN;

    for (int kb = 0; kb < 32; kb++) {
        const int buf = kb & 1;

        // RACE FIX: all warps must be done READING buffer buf^1 (tile kb-1)
        // before anyone issues cp.async writes of tile kb+1 into it.
        __syncthreads();

        if (kb + 1 < 32) {
            const int nbuf = buf ^ 1;
            const size_t kg1 = (size_t)(kb + 1) * 64;
            for (int i = tid; i < 1024; i += 256) {
                int r = i >> 4, c = i & 15;
                cp16(sb + (KS_OFF + nbuf * KBUF + r * KSTRIDE + c * 4) * 4,
                     kbase + (kg1 + r) * HD + c * 4);
                cp16(sb + (VS_OFF + nbuf * VBUF + r * VSTRIDE + c * 4) * 4,
                     vbase + (kg1 + r) * HD + c * 4);
            }
            cp_commit();
            cp_wait1();
        } else {
            cp_wait0();
        }
        __syncthreads();   // tile kb visible to all warps

        // ---- S = Q K^T : 64 MMAs ----
        const float* Kb = Ks + buf * KBUF;
        float sc[8][4];
        #pragma unroll
        for (int nb = 0; nb < 8; nb++)
            #pragma unroll
            for (int j = 0; j < 4; j++) sc[nb][j] = 0.f;

        #pragma unroll
        for (int kc = 0; kc < 8; kc++) {
            #pragma unroll
            for (int nb = 0; nb < 8; nb++) {
                u32 b0 = __float_as_uint(Kb[(nb * 8 + g) * KSTRIDE + kc * 8 + q]);
                u32 b1 = __float_as_uint(Kb[(nb * 8 + g) * KSTRIDE + kc * 8 + q + 4]);
                mma8(sc[nb], qa[kc], b0, b1);
            }
        }

        // ---- softmax (no running max) + P to smem ----
        const int kcol = kb * 64;
        #pragma unroll
        for (int nb = 0; nb < 8; nb++) {
            uint2 m0 = __ldg((const uint2*)(mrow0 + kcol + nb * 8 + 2 * q));
            uint2 m1 = __ldg((const uint2*)(mrow1 + kcol + nb * 8 + 2 * q));
            float p0 = m0.x ? 0.f : to_tf32(__expf(sc[nb][0] * SCALE));
            float p1 = m0.y ? 0.f : to_tf32(__expf(sc[nb][1] * SCALE));
            float p2 = m1.x ? 0.f : to_tf32(__expf(sc[nb][2] * SCALE));
            float p3 = m1.y ? 0.f : to_tf32(__expf(sc[nb][3] * SCALE));
            l0 += p0 + p1;
            l1 += p2 + p3;
            float2 w0; w0.x = p0; w0.y = p1;
            float2 w1; w1.x = p2; w1.y = p3;
            *(float2*)(Ps + r0 * PSTRIDE + nb * 8 + 2 * q) = w0;
            *(float2*)(Ps + r1 * PSTRIDE + nb * 8 + 2 * q) = w1;
        }
        __syncwarp();

        // ---- P A-fragments from smem (warp-local rows) ----
        u32 pa[8][4];
        #pragma unroll
        for (int kc = 0; kc < 8; kc++) {
            pa[kc][0] = __float_as_uint(Ps[r0 * PSTRIDE + kc * 8 + q]);
            pa[kc][1] = __float_as_uint(Ps[r1 * PSTRIDE + kc * 8 + q]);
            pa[kc][2] = __float_as_uint(Ps[r0 * PSTRIDE + kc * 8 + q + 4]);
            pa[kc][3] = __float_as_uint(Ps[r1 * PSTRIDE + kc * 8 + q + 4]);
        }

        // ---- O += P V : 64 MMAs ----
        const float* Vb = Vs + buf * VBUF;
        #pragma unroll
        for (int kc = 0; kc < 8; kc++) {
            #pragma unroll
            for (int nb = 0; nb < 8; nb++) {
                u32 b0 = __float_as_uint(Vb[(kc * 8 + q) * VSTRIDE + nb * 8 + g]);
                u32 b1 = __float_as_uint(Vb[(kc * 8 + q + 4) * VSTRIDE + nb * 8 + g]);
                mma8(oc[nb], pa[kc], b0, b1);
            }
        }
    }

    // ---- reduce l across the quad, normalize, park O in Ps ----
    l0 += __shfl_xor_sync(0xffffffffu, l0, 1);
    l0 += __shfl_xor_sync(0xffffffffu, l0, 2);
    l1 += __shfl_xor_sync(0xffffffffu, l1, 1);
    l1 += __shfl_xor_sync(0xffffffffu, l1, 2);
    const float inv0 = 1.0f / l0;
    const float inv1 = 1.0f / l1;

    #pragma unroll
    for (int nb = 0; nb < 8; nb++) {
        float2 w0, w1;
        w0.x = to_tf32(oc[nb][0] * inv0); w0.y = to_tf32(oc[nb][1] * inv0);
        w1.x = to_tf32(oc[nb][2] * inv1); w1.y = to_tf32(oc[nb][3] * inv1);
        *(float2*)(Ps + r0 * PSTRIDE + nb * 8 + 2 * q) = w0;
        *(float2*)(Ps + r1 * PSTRIDE + nb * 8 + 2 * q) = w1;
    }
    __syncthreads();

    // ---- stage Wo (tf32) into Ks area, row-major [g_out][h] pad 68 ----
    for (int i = tid; i < 4096; i += 256) {
        int go = i >> 6, h = i & 63;
        Ks[go * KSTRIDE + h] = to_tf32(Wo[i]);
    }
    __syncthreads();

    // ---- out = O_norm @ Wo^T + bo ----
    u32 oa[8][4];
    #pragma unroll
    for (int kc = 0; kc < 8; kc++) {
        oa[kc][0] = __float_as_uint(Ps[r0 * PSTRIDE + kc * 8 + q]);
        oa[kc][1] = __float_as_uint(Ps[r1 * PSTRIDE + kc * 8 + q]);
        oa[kc][2] = __float_as_uint(Ps[r0 * PSTRIDE + kc * 8 + q + 4]);
        oa[kc][3] = __float_as_uint(Ps[r1 * PSTRIDE + kc * 8 + q + 4]);
    }
    float rc[8][4];
    #pragma unroll
    for (int nb = 0; nb < 8; nb++)
        #pragma unroll
        for (int j = 0; j < 4; j++) rc[nb][j] = 0.f;
    #pragma unroll
    for (int kc = 0; kc < 8; kc++) {
        #pragma unroll
        for (int nb = 0; nb < 8; nb++) {
            u32 b0 = __float_as_uint(Ks[(nb * 8 + g) * KSTRIDE + kc * 8 + q]);
            u32 b1 = __float_as_uint(Ks[(nb * 8 + g) * KSTRIDE + kc * 8 + q + 4]);
            mma8(rc[nb], oa[kc], b0, b1);
        }
    }

    float* o0 = out + qg0 * HD;
    float* o1 = out + qg1 * HD;
    #pragma unroll
    for (int nb = 0; nb < 8; nb++) {
        const int col = nb * 8 + 2 * q;
        float2 w0, w1;
        w0.x = rc[nb][0] + bos[col];     w0.y = rc[nb][1] + bos[col + 1];
        w1.x = rc[nb][2] + bos[col];     w1.y = rc[nb][3] + bos[col + 1];
        *(float2*)(o0 + col) = w0;
        *(float2*)(o1 + col) = w1;
    }
}

// ---------------------------------------------------------------------------
extern "C" void kernel_launch(void* const* d_in, const int* in_sizes, int n_in,
                              void* d_out, int out_size)
{
    const float* x    = (const float*)d_in[0];
    const u32*   mask = (const u32*)d_in[1];
    const float* Wq   = (const float*)d_in[2];
    const float* bq   = (const float*)d_in[3];
    const float* Wk   = (const float*)d_in[4];
    const float* bk   = (const float*)d_in[5];
    const float* Wv   = (const float*)d_in[6];
    const float* bv   = (const float*)d_in[7];
    const float* Wo   = (const float*)d_in[8];
    const float* bo   = (const float*)d_in[9];
    float*       out  = (float*)d_out;

    const int proj_smem = (64 * XPAD + 128 * 64) * (int)sizeof(float);  // ~97.8 KB
    const int attn_smem = ATTN_FLOATS * (int)sizeof(float);             // 108.8 KB

    cudaFuncSetAttribute(qkv_proj_kernel,
                         cudaFuncAttributeMaxDynamicSharedMemorySize, proj_smem);
    cudaFuncSetAttribute(attn_mma_kernel,
                         cudaFuncAttributeMaxDynamicSharedMemorySize, attn_smem);

    qkv_proj_kernel<<<512, 256, proj_smem>>>(x, Wq, bq, Wk, bk, Wv, bv);
    attn_mma_kernel<<<dim3(16, 16), 256, attn_smem>>>(mask, Wo, bo, out);
}

// round 9
// speedup vs baseline: 4.3780x; 1.4222x over previous
#include <cuda_runtime.h>
#include <math.h>

#define NBT  16
#define SLEN 2048
#define HD   64
#define EDIM 256

// Q,K row-major [tok][h] (tf32-rounded). V TRANSPOSED: [bt][h][s] (tf32-rounded).
__device__ float g_q[NBT * SLEN * HD];
__device__ float g_k[NBT * SLEN * HD];
__device__ float g_v[NBT * HD * SLEN];

typedef unsigned int u32;

__device__ __forceinline__ u32 rna_bits(float x) {
    u32 r; asm("cvt.rna.tf32.f32 %0, %1;" : "=r"(r) : "f"(x)); return r;
}
__device__ __forceinline__ float to_tf32(float x) {
    return __uint_as_float(rna_bits(x));
}
__device__ __forceinline__ void cp16(u32 dst, const void* src) {
    asm volatile("cp.async.cg.shared.global [%0], [%1], 16;" :: "r"(dst), "l"(src));
}
__device__ __forceinline__ void cp_commit() { asm volatile("cp.async.commit_group;"); }
__device__ __forceinline__ void cp_wait1()  { asm volatile("cp.async.wait_group 1;"); }
__device__ __forceinline__ void cp_wait0()  { asm volatile("cp.async.wait_group 0;"); }

// m16n8k8 tf32 warp MMA. Slot mapping is caller-defined (relabeled k order).
__device__ __forceinline__ void mma8(float c[4], const u32 a[4], u32 b0, u32 b1) {
    asm volatile(
        "mma.sync.aligned.m16n8k8.row.col.f32.tf32.tf32.f32 "
        "{%0,%1,%2,%3}, {%4,%5,%6,%7}, {%8,%9}, {%0,%1,%2,%3};"
        : "+f"(c[0]), "+f"(c[1]), "+f"(c[2]), "+f"(c[3])
        : "r"(a[0]), "r"(a[1]), "r"(a[2]), "r"(a[3]), "r"(b0), "r"(b1));
}

// ---------------------------------------------------------------------------
// Kernel 1: QKV projection via warp MMA (tf32, x hi/lo split).
// CTA = 128 tokens, 256 threads (8 warps x 16 tokens). K-dim 256 in 4 chunks.
// smem: xs[2][128][72], ws[3][64][72], bs[3][64]
// ---------------------------------------------------------------------------
#define PXS_OFF 0
#define PXS_BUF 9216
#define PWS_OFF 18432
#define PWS_W   4608
#define PBS_OFF 32256
#define PROJ_FLOATS 32448   // 129.8 KB

__global__ __launch_bounds__(256) void qkv_proj_mma(
    const float* __restrict__ x,
    const float* __restrict__ Wq, const float* __restrict__ bq,
    const float* __restrict__ Wk, const float* __restrict__ bk,
    const float* __restrict__ Wv, const float* __restrict__ bv)
{
    extern __shared__ float sm[];
    const u32 sb = (u32)__cvta_generic_to_shared(sm);
    float* bs = sm + PBS_OFF;

    const int tid  = threadIdx.x;
    const int wid  = tid >> 5;
    const int lane = tid & 31;
    const int g    = lane >> 2;
    const int q    = lane & 3;
    const int t0   = blockIdx.x * 128;

    const float* Wmat[3] = {Wq, Wk, Wv};

    if (tid < 64) { bs[tid] = bq[tid]; bs[64 + tid] = bk[tid]; bs[128 + tid] = bv[tid]; }

    // prologue: stage xs chunk 0
    for (int i = tid; i < 2048; i += 256) {
        int r = i >> 4, c = i & 15;
        cp16(sb + (PXS_OFF + r * 72 + c * 4) * 4, x + (size_t)(t0 + r) * EDIM + c * 4);
    }
    cp_commit();

    float cc[3][8][4];
    #pragma unroll
    for (int w = 0; w < 3; w++)
        #pragma unroll
        for (int nb = 0; nb < 8; nb++)
            #pragma unroll
            for (int j = 0; j < 4; j++) cc[w][nb][j] = 0.f;

    const int rowA = wid * 16 + g;   // token row for a0/a2 (a1/a3: +8)

    for (int ch = 0; ch < 4; ch++) {
        const int buf = ch & 1;
        __syncthreads();   // xs[buf^1] reads (chunk ch-1) done; ws reads done

        if (ch + 1 < 4) {
            const int nbuf = buf ^ 1;
            for (int i = tid; i < 2048; i += 256) {
                int r = i >> 4, c = i & 15;
                cp16(sb + (PXS_OFF + nbuf * PXS_BUF + r * 72 + c * 4) * 4,
                     x + (size_t)(t0 + r) * EDIM + (ch + 1) * 64 + c * 4);
            }
            cp_commit();
        }

        // stage W chunk (LDG + RNA round + STS), 12 float4 per thread
        for (int i = tid; i < 3072; i += 256) {
            int w = i >> 10, rem = i & 1023;
            int go = rem >> 4, c4 = rem & 15;
            float4 v = *(const float4*)(Wmat[w] + go * EDIM + ch * 64 + c4 * 4);
            float4 o;
            o.x = to_tf32(v.x); o.y = to_tf32(v.y);
            o.z = to_tf32(v.z); o.w = to_tf32(v.w);
            *(float4*)(sm + PWS_OFF + w * PWS_W + go * 72 + c4 * 4) = o;
        }

        if (ch + 1 < 4) cp_wait1(); else cp_wait0();
        __syncthreads();

        const float* xb = sm + PXS_OFF + buf * PXS_BUF;
        #pragma unroll
        for (int kc = 0; kc < 8; kc++) {
            // A frags (relabeled: slot q -> col kc*8+2q, slot q+4 -> +1)
            float2 ra0 = *(const float2*)(xb + rowA * 72 + kc * 8 + 2 * q);
            float2 ra1 = *(const float2*)(xb + (rowA + 8) * 72 + kc * 8 + 2 * q);
            u32 ah[4], al[4];
            ah[0] = rna_bits(ra0.x); ah[1] = rna_bits(ra1.x);
            ah[2] = rna_bits(ra0.y); ah[3] = rna_bits(ra1.y);
            al[0] = rna_bits(ra0.x - __uint_as_float(ah[0]));
            al[1] = rna_bits(ra1.x - __uint_as_float(ah[1]));
            al[2] = rna_bits(ra0.y - __uint_as_float(ah[2]));
            al[3] = rna_bits(ra1.y - __uint_as_float(ah[3]));

            #pragma unroll
            for (int w = 0; w < 3; w++) {
                const float* wb = sm + PWS_OFF + w * PWS_W;
                u32 bb[8][2];
                #pragma unroll
                for (int nb = 0; nb < 8; nb++) {
                    float2 b = *(const float2*)(wb + (nb * 8 + g) * 72 + kc * 8 + 2 * q);
                    bb[nb][0] = __float_as_uint(b.x);
                    bb[nb][1] = __float_as_uint(b.y);
                    mma8(cc[w][nb], ah, bb[nb][0], bb[nb][1]);
                }
                #pragma unroll
                for (int nb = 0; nb < 8; nb++)
                    mma8(cc[w][nb], al, bb[nb][0], bb[nb][1]);
            }
        }
    }

    // epilogue: +bias, RNA, store. Q/K natural float2; V transposed scalar.
    const int tok0 = t0 + rowA;
    const int bt   = tok0 >> 11;
    const int sl   = tok0 & 2047;
    float* vt = g_v + (size_t)bt * HD * SLEN;

    #pragma unroll
    for (int w = 0; w < 3; w++) {
        #pragma unroll
        for (int nb = 0; nb < 8; nb++) {
            const int h0 = nb * 8 + 2 * q;
            float c0 = to_tf32(cc[w][nb][0] + bs[w * 64 + h0]);
            float c1 = to_tf32(cc[w][nb][1] + bs[w * 64 + h0 + 1]);
            float c2 = to_tf32(cc[w][nb][2] + bs[w * 64 + h0]);
            float c3 = to_tf32(cc[w][nb][3] + bs[w * 64 + h0 + 1]);
            if (w < 2) {
                float* ob = (w == 0 ? g_q : g_k);
                float2 v0; v0.x = c0; v0.y = c1;
                float2 v1; v1.x = c2; v1.y = c3;
                *(float2*)(ob + (size_t)tok0 * HD + h0) = v0;
                *(float2*)(ob + (size_t)(tok0 + 8) * HD + h0) = v1;
            } else {
                vt[(size_t)h0 * SLEN + sl]           = c0;
                vt[(size_t)(h0 + 1) * SLEN + sl]     = c1;
                vt[(size_t)h0 * SLEN + sl + 8]       = c2;
                vt[(size_t)(h0 + 1) * SLEN + sl + 8] = c3;
            }
        }
    }
}

// ---------------------------------------------------------------------------
// Kernel 2: warp-MMA tf32 flash attention + fused Wo (vectorized fragments).
// CTA = 128 queries, 8 warps. K tiles natural [s][h]; V tiles transposed [h][s].
// All B/A fragment loads are LDS.64 via k-slot relabeling (slot q -> 2q, 2q+1).
// ---------------------------------------------------------------------------
#define KS_OFF 0
#define KSTRIDE 72
#define KBUF 4608
#define VS_OFF 9216
#define VSTRIDE 72
#define VBUF 4608
#define PS_OFF 18432
#define PSTRIDE 72
#define BO_OFF 27648
#define ATTN_FLOATS 27712   // 110.85 KB

#define SCALE 0.0625f

__global__ __launch_bounds__(256) void attn_mma_kernel(
    const u32* __restrict__ mask,
    const float* __restrict__ Wo, const float* __restrict__ bo,
    float* __restrict__ out)
{
    extern __shared__ float sm[];
    float* Ks = sm + KS_OFF;
    float* Vs = sm + VS_OFF;
    float* Ps = sm + PS_OFF;
    float* bos = sm + BO_OFF;
    const u32 sb = (u32)__cvta_generic_to_shared(sm);

    const int tid  = threadIdx.x;
    const int wid  = tid >> 5;
    const int lane = tid & 31;
    const int g    = lane >> 2;
    const int q    = lane & 3;
    const int bt   = blockIdx.y;
    const int q0   = blockIdx.x * 128;

    const int r0 = wid * 16 + g;
    const int r1 = r0 + 8;
    const size_t qg0 = (size_t)bt * SLEN + q0 + r0;
    const size_t qg1 = qg0 + 8;

    const float* kbase  = g_k + ((size_t)bt * SLEN) * HD;
    const float* vtbase = g_v + (size_t)bt * HD * SLEN;

    // Q A-fragments (relabeled): slot q -> h = kc*8+2q (a0), +1 (a2)
    u32 qa[8][4];
    {
        const float* qrow0 = g_q + qg0 * HD;
        const float* qrow1 = g_q + qg1 * HD;
        #pragma unroll
        for (int kc = 0; kc < 8; kc++) {
            float2 f0 = __ldg((const float2*)(qrow0 + kc * 8 + 2 * q));
            float2 f1 = __ldg((const float2*)(qrow1 + kc * 8 + 2 * q));
            qa[kc][0] = __float_as_uint(f0.x);
            qa[kc][1] = __float_as_uint(f1.x);
            qa[kc][2] = __float_as_uint(f0.y);
            qa[kc][3] = __float_as_uint(f1.y);
        }
    }

    // stage tile 0: K rows = key s (natural), V rows = h (transposed source)
    for (int i = tid; i < 1024; i += 256) {
        int r = i >> 4, c = i & 15;
        cp16(sb + (KS_OFF + r * KSTRIDE + c * 4) * 4, kbase + (size_t)r * HD + c * 4);
        cp16(sb + (VS_OFF + r * VSTRIDE + c * 4) * 4, vtbase + (size_t)r * SLEN + c * 4);
    }
    cp_commit();

    if (tid < 64) bos[tid] = bo[tid];

    float oc[8][4];
    #pragma unroll
    for (int nb = 0; nb < 8; nb++)
        #pragma unroll
        for (int j = 0; j < 4; j++) oc[nb][j] = 0.f;
    float l0 = 0.f, l1 = 0.f;

    const u32* mrow0 = mask + qg0 * SLEN;
    const u32* mrow1 = mask + qg1 * SLEN;

    for (int kb = 0; kb < 32; kb++) {
        const int buf = kb & 1;
        __syncthreads();   // all reads of buf^1 (tile kb-1) complete

        if (kb + 1 < 32) {
            const int nbuf = buf ^ 1;
            const size_t kg1 = (size_t)(kb + 1) * 64;
            for (int i = tid; i < 1024; i += 256) {
                int r = i >> 4, c = i & 15;
                cp16(sb + (KS_OFF + nbuf * KBUF + r * KSTRIDE + c * 4) * 4,
                     kbase + (kg1 + r) * HD + c * 4);
                cp16(sb + (VS_OFF + nbuf * VBUF + r * VSTRIDE + c * 4) * 4,
                     vtbase + (size_t)r * SLEN + kg1 + c * 4);
            }
            cp_commit();
            cp_wait1();
        } else {
            cp_wait0();
        }
        __syncthreads();

        // ---- S = Q K^T : B frags LDS.64 (K natural, relabeled slots) ----
        const float* Kb = Ks + buf * KBUF;
        float sc[8][4];
        #pragma unroll
        for (int nb = 0; nb < 8; nb++)
            #pragma unroll
            for (int j = 0; j < 4; j++) sc[nb][j] = 0.f;

        #pragma unroll
        for (int kc = 0; kc < 8; kc++) {
            #pragma unroll
            for (int nb = 0; nb < 8; nb++) {
                float2 b = *(const float2*)(Kb + (nb * 8 + g) * KSTRIDE + kc * 8 + 2 * q);
                mma8(sc[nb], qa[kc], __float_as_uint(b.x), __float_as_uint(b.y));
            }
        }

        // ---- softmax (no running max) + P to smem (natural cols) ----
        const int kcol = kb * 64;
        #pragma unroll
        for (int nb = 0; nb < 8; nb++) {
            uint2 m0 = __ldg((const uint2*)(mrow0 + kcol + nb * 8 + 2 * q));
            uint2 m1 = __ldg((const uint2*)(mrow1 + kcol + nb * 8 + 2 * q));
            float p0 = m0.x ? 0.f : to_tf32(__expf(sc[nb][0] * SCALE));
            float p1 = m0.y ? 0.f : to_tf32(__expf(sc[nb][1] * SCALE));
            float p2 = m1.x ? 0.f : to_tf32(__expf(sc[nb][2] * SCALE));
            float p3 = m1.y ? 0.f : to_tf32(__expf(sc[nb][3] * SCALE));
            l0 += p0 + p1;
            l1 += p2 + p3;
            float2 w0; w0.x = p0; w0.y = p1;
            float2 w1; w1.x = p2; w1.y = p3;
            *(float2*)(Ps + r0 * PSTRIDE + nb * 8 + 2 * q) = w0;
            *(float2*)(Ps + r1 * PSTRIDE + nb * 8 + 2 * q) = w1;
        }
        __syncwarp();

        // ---- P A-frags: LDS.64 pairs (relabeled) ----
        u32 pa[8][4];
        #pragma unroll
        for (int kc = 0; kc < 8; kc++) {
            float2 f0 = *(const float2*)(Ps + r0 * PSTRIDE + kc * 8 + 2 * q);
            float2 f1 = *(const float2*)(Ps + r1 * PSTRIDE + kc * 8 + 2 * q);
            pa[kc][0] = __float_as_uint(f0.x);
            pa[kc][1] = __float_as_uint(f1.x);
            pa[kc][2] = __float_as_uint(f0.y);
            pa[kc][3] = __float_as_uint(f1.y);
        }

        // ---- O += P V : B frags LDS.64 from transposed V tile ----
        const float* Vb = Vs + buf * VBUF;
        #pragma unroll
        for (int kc = 0; kc < 8; kc++) {
            #pragma unroll
            for (int nb = 0; nb < 8; nb++) {
                float2 b = *(const float2*)(Vb + (nb * 8 + g) * VSTRIDE + kc * 8 + 2 * q);
                mma8(oc[nb], pa[kc], __float_as_uint(b.x), __float_as_uint(b.y));
            }
        }
    }

    // ---- reduce l across quad, normalize, park O in Ps ----
    l0 += __shfl_xor_sync(0xffffffffu, l0, 1);
    l0 += __shfl_xor_sync(0xffffffffu, l0, 2);
    l1 += __shfl_xor_sync(0xffffffffu, l1, 1);
    l1 += __shfl_xor_sync(0xffffffffu, l1, 2);
    const float inv0 = 1.0f / l0;
    const float inv1 = 1.0f / l1;

    #pragma unroll
    for (int nb = 0; nb < 8; nb++) {
        float2 w0, w1;
        w0.x = to_tf32(oc[nb][0] * inv0); w0.y = to_tf32(oc[nb][1] * inv0);
        w1.x = to_tf32(oc[nb][2] * inv1); w1.y = to_tf32(oc[nb][3] * inv1);
        *(float2*)(Ps + r0 * PSTRIDE + nb * 8 + 2 * q) = w0;
        *(float2*)(Ps + r1 * PSTRIDE + nb * 8 + 2 * q) = w1;
    }
    __syncthreads();

    // ---- stage Wo (RNA) natural [g_out][h] into Ks area, stride 72 ----
    for (int i = tid; i < 4096; i += 256) {
        int go = i >> 6, h = i & 63;
        Ks[go * KSTRIDE + h] = to_tf32(Wo[i]);
    }
    __syncthreads();

    // ---- out = O_norm @ Wo^T + bo (all frags LDS.64) ----
    u32 oa[8][4];
    #pragma unroll
    for (int kc = 0; kc < 8; kc++) {
        float2 f0 = *(const float2*)(Ps + r0 * PSTRIDE + kc * 8 + 2 * q);
        float2 f1 = *(const float2*)(Ps + r1 * PSTRIDE + kc * 8 + 2 * q);
        oa[kc][0] = __float_as_uint(f0.x);
        oa[kc][1] = __float_as_uint(f1.x);
        oa[kc][2] = __float_as_uint(f0.y);
        oa[kc][3] = __float_as_uint(f1.y);
    }
    float rc[8][4];
    #pragma unroll
    for (int nb = 0; nb < 8; nb++)
        #pragma unroll
        for (int j = 0; j < 4; j++) rc[nb][j] = 0.f;
    #pragma unroll
    for (int kc = 0; kc < 8; kc++) {
        #pragma unroll
        for (int nb = 0; nb < 8; nb++) {
            float2 b = *(const float2*)(Ks + (nb * 8 + g) * KSTRIDE + kc * 8 + 2 * q);
            mma8(rc[nb], oa[kc], __float_as_uint(b.x), __float_as_uint(b.y));
        }
    }

    float* o0 = out + qg0 * HD;
    float* o1 = out + qg1 * HD;
    #pragma unroll
    for (int nb = 0; nb < 8; nb++) {
        const int col = nb * 8 + 2 * q;
        float2 w0, w1;
        w0.x = rc[nb][0] + bos[col];     w0.y = rc[nb][1] + bos[col + 1];
        w1.x = rc[nb][2] + bos[col];     w1.y = rc[nb][3] + bos[col + 1];
        *(float2*)(o0 + col) = w0;
        *(float2*)(o1 + col) = w1;
    }
}

// ---------------------------------------------------------------------------
extern "C" void kernel_launch(void* const* d_in, const int* in_sizes, int n_in,
                              void* d_out, int out_size)
{
    const float* x    = (const float*)d_in[0];
    const u32*   mask = (const u32*)d_in[1];
    const float* Wq   = (const float*)d_in[2];
    const float* bq   = (const float*)d_in[3];
    const float* Wk   = (const float*)d_in[4];
    const float* bk   = (const float*)d_in[5];
    const float* Wv   = (const float*)d_in[6];
    const float* bv   = (const float*)d_in[7];
    const float* Wo   = (const float*)d_in[8];
    const float* bo   = (const float*)d_in[9];
    float*       out  = (float*)d_out;

    const int proj_smem = PROJ_FLOATS * (int)sizeof(float);   // 129.8 KB
    const int attn_smem = ATTN_FLOATS * (int)sizeof(float);   // 110.85 KB

    cudaFuncSetAttribute(qkv_proj_mma,
                         cudaFuncAttributeMaxDynamicSharedMemorySize, proj_smem);
    cudaFuncSetAttribute(attn_mma_kernel,
                         cudaFuncAttributeMaxDynamicSharedMemorySize, attn_smem);

    qkv_proj_mma<<<256, 256, proj_smem>>>(x, Wq, bq, Wk, bk, Wv, bv);
    attn_mma_kernel<<<dim3(16, 16), 256, attn_smem>>>(mask, Wo, bo, out);
}